// round 1
// baseline (speedup 1.0000x reference)
#include <cuda_runtime.h>
#include <cuda_bf16.h>

// Conv2d: N=32, C=128, H=W=56, OC=256, 3x3, pad=1, stride=1, fp32.
// Implicit GEMM: M = 32*56*56 = 100352 (pixels), N = 256 (oc), K = 128*9 = 1152.
// Tile: BM=128 x BN=128 x BK=16, 256 threads, 8x8 accumulators per thread.

#define N_IMG   32
#define C_IN    128
#define H_DIM   56
#define W_DIM   56
#define OC_DIM  256
#define HW      (H_DIM * W_DIM)        // 3136
#define K_TOTAL (C_IN * 9)             // 1152
#define M_TOTAL (N_IMG * HW)           // 100352

#define BM 128
#define BN 128
#define BK 16
#define TM 8
#define TN 8
#define THREADS 256

__global__ __launch_bounds__(THREADS)
void conv2d_igemm_kernel(const float* __restrict__ in,
                         const float* __restrict__ wgt,
                         const float* __restrict__ bias,
                         float* __restrict__ out)
{
    __shared__ float As[BK][BM];        // A: input patches, [k][m]
    __shared__ float Bs[BK][BN + 4];    // B: weights, [k][oc], pad 4 to kill store conflicts

    const int tid     = threadIdx.x;
    const int m_base  = blockIdx.x * BM;   // 784 tiles
    const int oc_base = blockIdx.y * BN;   // 2 tiles

    // ---- A gather-load mapping: this thread always loads m_local = tid & 127,
    //      for k_local = (tid>>7) + 2*i, i = 0..7  (256 thr cover 128m x 16k)
    const int a_m   = tid & 127;
    const int a_k0  = tid >> 7;            // 0 or 1
    const int m_g   = m_base + a_m;
    const int n_img = m_g / HW;
    const int hw    = m_g - n_img * HW;
    const int h     = hw / W_DIM;
    const int w     = hw - h * W_DIM;
    const float* in_n = in + (long)n_img * (C_IN * HW);

    // ---- B load mapping: k_local = tid & 15 (contiguous across threads for
    //      coalescing, since weights are k-contiguous), oc_local = (tid>>4)+16*i
    const int b_k   = tid & 15;
    const int b_oc0 = tid >> 4;

    // ---- compute mapping: tx -> m (fast/contiguous dim), ty -> oc
    const int tx = tid & 15;
    const int ty = tid >> 4;

    float acc[TN][TM];
    #pragma unroll
    for (int i = 0; i < TN; i++)
        #pragma unroll
        for (int j = 0; j < TM; j++)
            acc[i][j] = 0.0f;

    for (int kb = 0; kb < K_TOTAL; kb += BK) {
        // load A tile (gather from input with implicit im2col)
        #pragma unroll
        for (int i = 0; i < 8; i++) {
            const int k  = kb + a_k0 + 2 * i;
            const int c  = k / 9;
            const int rs = k - c * 9;
            const int r  = rs / 3;
            const int s  = rs - r * 3;
            const int ih = h + r - 1;
            const int iw = w + s - 1;
            float v = 0.0f;
            if ((unsigned)ih < (unsigned)H_DIM && (unsigned)iw < (unsigned)W_DIM)
                v = __ldg(in_n + c * HW + ih * W_DIM + iw);
            As[a_k0 + 2 * i][a_m] = v;
        }
        // load B tile (weights OIHW: row oc is K_TOTAL contiguous floats)
        #pragma unroll
        for (int i = 0; i < 8; i++) {
            const int oc = oc_base + b_oc0 + 16 * i;
            Bs[b_k][b_oc0 + 16 * i] = __ldg(wgt + (long)oc * K_TOTAL + kb + b_k);
        }
        __syncthreads();

        #pragma unroll
        for (int kk = 0; kk < BK; kk++) {
            float a_frag[TM], b_frag[TN];
            #pragma unroll
            for (int j = 0; j < TM; j++) a_frag[j] = As[kk][tx * TM + j];
            #pragma unroll
            for (int i = 0; i < TN; i++) b_frag[i] = Bs[kk][ty * TN + i];
            #pragma unroll
            for (int i = 0; i < TN; i++)
                #pragma unroll
                for (int j = 0; j < TM; j++)
                    acc[i][j] = fmaf(b_frag[i], a_frag[j], acc[i][j]);
        }
        __syncthreads();
    }

    // ---- epilogue: add bias, scatter to NCHW output
    #pragma unroll
    for (int i = 0; i < TN; i++) {
        const int oc = oc_base + ty * TN + i;
        const float bv = __ldg(bias + oc);
        #pragma unroll
        for (int j = 0; j < TM; j++) {
            const int m   = m_base + tx * TM + j;
            const int nn  = m / HW;
            const int phw = m - nn * HW;
            out[((long)nn * OC_DIM + oc) * HW + phw] = acc[i][j] + bv;
        }
    }
}

extern "C" void kernel_launch(void* const* d_in, const int* in_sizes, int n_in,
                              void* d_out, int out_size)
{
    const float* in   = (const float*)d_in[0];
    const float* wgt  = (const float*)d_in[1];
    const float* bias = (const float*)d_in[2];
    float* out        = (float*)d_out;

    dim3 grid(M_TOTAL / BM, OC_DIM / BN, 1);   // 784 x 2
    conv2d_igemm_kernel<<<grid, THREADS>>>(in, wgt, bias, out);
}

// round 3
// speedup vs baseline: 3.1116x; 3.1116x over previous
#include <cuda_runtime.h>
#include <cstdint>

// Conv2d 3x3 s1 p1, NCHW fp32: N=32, C=128, H=W=56, OC=256.
// Implicit GEMM on mma.sync.m16n8k8.tf32 (baseline PTX — tcgen05 is rejected
// by this toolchain's .target sm_103):
//   M = 32*56*56 = 100352, N = 256, K = 1152.
// CTA tile 128x128x32, 8 warps (4M x 2N), warp tile 32x64.
// cp.async double-buffered smem, zfill for im2col padding.

#define N_IMG   32
#define C_IN    128
#define H_DIM   56
#define W_DIM   56
#define OC_DIM  256
#define HW      (H_DIM * W_DIM)        // 3136
#define K_TOTAL 1152
#define M_TOTAL (N_IMG * HW)           // 100352

#define BM 128
#define BN 128
#define BK 32
#define THREADS 256
#define NSTAGES (K_TOTAL / BK)         // 36

#define A_STRIDE 136                    // floats; bank = (8k + m) % 32 -> conflict-free
#define B_STRIDE 36                     // floats; bank = (4n + k) % 32 -> conflict-free
#define A_BYTES (BK * A_STRIDE * 4)     // 17408
#define B_BYTES (BN * B_STRIDE * 4)     // 18432
#define STAGE_BYTES (A_BYTES + B_BYTES) // 35840
#define SMEM_TOTAL (2 * STAGE_BYTES)    // 71680

__device__ __forceinline__ uint32_t smem_u32(const void* p) {
    uint32_t a;
    asm("{ .reg .u64 t; cvta.to.shared.u64 t, %1; cvt.u32.u64 %0, t; }" : "=r"(a) : "l"(p));
    return a;
}
__device__ __forceinline__ uint32_t f2tf32(float f) {
    uint32_t u;
    asm("cvt.rna.tf32.f32 %0, %1;" : "=r"(u) : "f"(f));
    return u;
}
__device__ __forceinline__ void cp4_zfill(uint32_t dst, const void* src, uint32_t sz) {
    asm volatile("cp.async.ca.shared.global [%0], [%1], 4, %2;"
                 :: "r"(dst), "l"(src), "r"(sz) : "memory");
}
__device__ __forceinline__ void cp16(uint32_t dst, const void* src) {
    asm volatile("cp.async.cg.shared.global [%0], [%1], 16;"
                 :: "r"(dst), "l"(src) : "memory");
}
__device__ __forceinline__ void mma_tf32(float& c0, float& c1, float& c2, float& c3,
                                         uint32_t a0, uint32_t a1, uint32_t a2, uint32_t a3,
                                         uint32_t b0, uint32_t b1) {
    asm volatile(
        "mma.sync.aligned.m16n8k8.row.col.f32.tf32.tf32.f32 "
        "{%0,%1,%2,%3}, {%4,%5,%6,%7}, {%8,%9}, {%0,%1,%2,%3};"
        : "+f"(c0), "+f"(c1), "+f"(c2), "+f"(c3)
        : "r"(a0), "r"(a1), "r"(a2), "r"(a3), "r"(b0), "r"(b1));
}

__global__ void __launch_bounds__(THREADS, 2)
conv2d_mma_kernel(const float* __restrict__ in,
                  const float* __restrict__ wgt,
                  const float* __restrict__ bias,
                  float* __restrict__ out)
{
    extern __shared__ char smem_raw[];
    const uint32_t sbase = smem_u32(smem_raw);

    const int tid     = threadIdx.x;
    const int lane    = tid & 31;
    const int wid     = tid >> 5;
    const int m_base  = blockIdx.x * BM;
    const int oc_base = blockIdx.y * BN;

    // ---- A im2col gather mapping: thread owns pixel m_local = tid & 127,
    //      k-range a_kq..a_kq+15 (two thread groups cover BK=32) ----
    const int a_m   = tid & 127;
    const int a_kq  = (tid >> 7) * 16;     // 0 or 16
    const int m_g   = m_base + a_m;
    const int n_img = m_g / HW;
    const int hw    = m_g - n_img * HW;
    const int h     = hw / W_DIM;
    const int w     = hw - h * W_DIM;
    const float* in_p = in + (size_t)n_img * (C_IN * HW) + hw;   // center pixel, c=0

    // precompute 3x3 tap offsets + validity (independent of c)
    int   off9[9];
    uint32_t sz9[9];
    #pragma unroll
    for (int rs = 0; rs < 9; rs++) {
        const int r = rs / 3, s = rs - 3 * r;
        const int ih = h + r - 1, iw = w + s - 1;
        const bool ok = ((unsigned)ih < (unsigned)H_DIM) && ((unsigned)iw < (unsigned)W_DIM);
        off9[rs] = ok ? ((r - 1) * W_DIM + (s - 1)) : 0;
        sz9[rs]  = ok ? 4u : 0u;
    }

    // ---- B (weights) load mapping: vector v = tid + 256*i; n = v>>3, q = v&7 ----
    const int b_n = tid >> 3;
    const int b_q = tid & 7;
    const float* wgt_p = wgt + (size_t)(oc_base + b_n) * K_TOTAL + b_q * 4;

    auto load_stage = [&](int s, int buf) {
        const int kb = s * BK;
        const uint32_t abase = sbase + buf * STAGE_BYTES;
        const uint32_t bbase = abase + A_BYTES;
        // A: 16 gathered 4B cp.async (zfill on padding)
        #pragma unroll
        for (int i = 0; i < 16; i++) {
            const int k  = kb + a_kq + i;
            const int c  = k / 9;
            const int rs = k - 9 * c;
            const float* src = in_p + c * HW + off9[rs];
            const uint32_t dst = abase + (uint32_t)(((a_kq + i) * A_STRIDE + a_m) * 4);
            cp4_zfill(dst, src, sz9[rs]);
        }
        // B: 4 x 16B cp.async
        #pragma unroll
        for (int i = 0; i < 4; i++) {
            const int n = b_n + 32 * i;
            const float* src = wgt_p + (size_t)(32 * i) * K_TOTAL + kb;
            const uint32_t dst = bbase + (uint32_t)((n * B_STRIDE + b_q * 4) * 4);
            cp16(dst, src);
        }
        asm volatile("cp.async.commit_group;" ::: "memory");
    };

    // ---- warp compute mapping: 4(M) x 2(N) warps, warp tile 32x64 ----
    const int wm  = wid & 3;
    const int wn  = wid >> 2;
    const int grp = lane >> 2;          // 0..7
    const int tig = lane & 3;           // 0..3

    float acc[2][8][4];
    #pragma unroll
    for (int mi = 0; mi < 2; mi++)
        #pragma unroll
        for (int ni = 0; ni < 8; ni++)
            #pragma unroll
            for (int c = 0; c < 4; c++)
                acc[mi][ni][c] = 0.0f;

    load_stage(0, 0);

    for (int s = 0; s < NSTAGES; s++) {
        if (s + 1 < NSTAGES) {
            load_stage(s + 1, (s + 1) & 1);
            asm volatile("cp.async.wait_group 1;" ::: "memory");
        } else {
            asm volatile("cp.async.wait_group 0;" ::: "memory");
        }
        __syncthreads();

        const float* As = (const float*)(smem_raw + (s & 1) * STAGE_BYTES);
        const float* Bs = (const float*)(smem_raw + (s & 1) * STAGE_BYTES + A_BYTES);

        #pragma unroll
        for (int ks = 0; ks < 4; ks++) {
            const int k0 = ks * 8 + tig;
            uint32_t a[2][4];
            #pragma unroll
            for (int mi = 0; mi < 2; mi++) {
                const int row = wm * 32 + mi * 16 + grp;
                a[mi][0] = f2tf32(As[k0 * A_STRIDE + row]);
                a[mi][1] = f2tf32(As[k0 * A_STRIDE + row + 8]);
                a[mi][2] = f2tf32(As[(k0 + 4) * A_STRIDE + row]);
                a[mi][3] = f2tf32(As[(k0 + 4) * A_STRIDE + row + 8]);
            }
            uint32_t b[8][2];
            #pragma unroll
            for (int ni = 0; ni < 8; ni++) {
                const int col = wn * 64 + ni * 8 + grp;
                b[ni][0] = f2tf32(Bs[col * B_STRIDE + k0]);
                b[ni][1] = f2tf32(Bs[col * B_STRIDE + k0 + 4]);
            }
            #pragma unroll
            for (int mi = 0; mi < 2; mi++)
                #pragma unroll
                for (int ni = 0; ni < 8; ni++)
                    mma_tf32(acc[mi][ni][0], acc[mi][ni][1], acc[mi][ni][2], acc[mi][ni][3],
                             a[mi][0], a[mi][1], a[mi][2], a[mi][3],
                             b[ni][0], b[ni][1]);
        }
        __syncthreads();
    }

    // ---- epilogue: +bias, scatter to NCHW ----
    #pragma unroll
    for (int mi = 0; mi < 2; mi++) {
        const int row0 = m_base + wm * 32 + mi * 16 + grp;
        #pragma unroll
        for (int half = 0; half < 2; half++) {
            const int m   = row0 + 8 * half;
            const int nn  = m / HW;
            const int phw = m - nn * HW;
            float* op = out + (size_t)nn * OC_DIM * HW + phw;
            #pragma unroll
            for (int ni = 0; ni < 8; ni++) {
                const int oc = oc_base + wn * 64 + ni * 8 + 2 * tig;
                const float b0 = __ldg(bias + oc);
                const float b1 = __ldg(bias + oc + 1);
                op[(size_t)oc * HW]       = acc[mi][ni][2 * half + 0] + b0;
                op[(size_t)(oc + 1) * HW] = acc[mi][ni][2 * half + 1] + b1;
            }
        }
    }
}

extern "C" void kernel_launch(void* const* d_in, const int* in_sizes, int n_in,
                              void* d_out, int out_size)
{
    const float* in   = (const float*)d_in[0];
    const float* wgt  = (const float*)d_in[1];
    const float* bias = (const float*)d_in[2];
    float* out        = (float*)d_out;

    cudaFuncSetAttribute(conv2d_mma_kernel,
                         cudaFuncAttributeMaxDynamicSharedMemorySize, SMEM_TOTAL);
    dim3 grid(M_TOTAL / BM, OC_DIM / BN, 1);   // 784 x 2
    conv2d_mma_kernel<<<grid, THREADS, SMEM_TOTAL>>>(in, wgt, bias, out);
}

// round 4
// speedup vs baseline: 3.3446x; 1.0749x over previous
#include <cuda_runtime.h>
#include <cstdint>

// Conv2d 3x3 s1 p1 NCHW fp32: N=32,C=128,H=W=56,OC=256.
// Implicit GEMM, mma.sync.m16n8k8.tf32. K reordered as k' = tap*128 + c.
// Prep kernels pre-convert input & weights to TF32 (weights also reordered
// into fragment layout), so the main loop has no CVTs and only LDS.128 reads.

#define N_IMG   32
#define C_IN    128
#define H_DIM   56
#define W_DIM   56
#define OC_DIM  256
#define HW      3136
#define K_TOTAL 1152
#define M_TOTAL 100352

#define BM 128
#define BN 128
#define BK 32
#define THREADS 256
#define NSTAGES 36                      // K_TOTAL / BK

#define STAGE_BYTES 32768               // A 16KB + B 16KB (fragment order)
#define SMEM_TOTAL  (3 * STAGE_BYTES)   // 96KB, 3-stage ring

__device__ __align__(16) float    g_in_t[N_IMG * C_IN * HW];   // tf32 input copy
__device__ __align__(16) uint32_t g_w_t[OC_DIM * K_TOTAL];     // tf32 frag weights

__device__ __forceinline__ uint32_t smem_u32(const void* p) {
    uint32_t a;
    asm("{ .reg .u64 t; cvta.to.shared.u64 t, %1; cvt.u32.u64 %0, t; }" : "=r"(a) : "l"(p));
    return a;
}
__device__ __forceinline__ uint32_t f2tf32(float f) {
    uint32_t u;
    asm("cvt.rna.tf32.f32 %0, %1;" : "=r"(u) : "f"(f));
    return u;
}
__device__ __forceinline__ void cp4_zfill(uint32_t dst, const void* src, uint32_t sz) {
    asm volatile("cp.async.ca.shared.global [%0], [%1], 4, %2;"
                 :: "r"(dst), "l"(src), "r"(sz) : "memory");
}
__device__ __forceinline__ void cp16(uint32_t dst, const void* src) {
    asm volatile("cp.async.cg.shared.global [%0], [%1], 16;"
                 :: "r"(dst), "l"(src) : "memory");
}
__device__ __forceinline__ void lds128(uint32_t* r, uint32_t addr) {
    asm volatile("ld.shared.v4.u32 {%0,%1,%2,%3}, [%4];"
                 : "=r"(r[0]), "=r"(r[1]), "=r"(r[2]), "=r"(r[3]) : "r"(addr));
}
__device__ __forceinline__ void mma_tf32(float* c,
                                         const uint32_t* a, uint32_t b0, uint32_t b1) {
    asm volatile(
        "mma.sync.aligned.m16n8k8.row.col.f32.tf32.tf32.f32 "
        "{%0,%1,%2,%3}, {%4,%5,%6,%7}, {%8,%9}, {%0,%1,%2,%3};"
        : "+f"(c[0]), "+f"(c[1]), "+f"(c[2]), "+f"(c[3])
        : "r"(a[0]), "r"(a[1]), "r"(a[2]), "r"(a[3]), "r"(b0), "r"(b1));
}

// ---- prep: input -> tf32 bits, same layout ----
__global__ void prep_in_kernel(const float* __restrict__ in) {
    const int i = blockIdx.x * blockDim.x + threadIdx.x;   // float4 index
    float4 v = ((const float4*)in)[i];
    float4 o;
    o.x = __uint_as_float(f2tf32(v.x));
    o.y = __uint_as_float(f2tf32(v.y));
    o.z = __uint_as_float(f2tf32(v.z));
    o.w = __uint_as_float(f2tf32(v.w));
    ((float4*)g_in_t)[i] = o;
}

// ---- prep: weights -> tf32, fragment order keyed by k' = rs*128 + c ----
__global__ void prep_w_kernel(const float* __restrict__ w) {
    const int idx = blockIdx.x * blockDim.x + threadIdx.x;  // oc*1152 + c*9 + rs
    const int oc = idx / K_TOTAL;
    const int kf = idx - oc * K_TOTAL;
    const int c  = kf / 9;
    const int rs = kf - c * 9;
    const int kp = rs * 128 + c;             // reordered K
    const int s   = kp >> 5;
    const int kl  = kp & 31;
    const int ks  = kl >> 3;
    const int tig = kl & 3;
    const int kh  = (kl >> 2) & 1;
    const int nh  = oc >> 7;
    const int ocl = oc & 127;
    const int tp  = ocl >> 4;
    const int tpo = (ocl >> 3) & 1;
    const int grp = ocl & 7;
    const int word = ((s * 2 + nh) * 4 + ks) * 1024
                   + tp * 128 + grp * 16 + tig * 4 + tpo * 2 + kh;
    g_w_t[word] = f2tf32(w[idx]);
}

__global__ void __launch_bounds__(THREADS, 2)
conv2d_mma_kernel(const float* __restrict__ bias, float* __restrict__ out)
{
    extern __shared__ char smem_raw[];
    const uint32_t sbase = smem_u32(smem_raw);

    const int tid     = threadIdx.x;
    const int lane    = tid & 31;
    const int wid     = tid >> 5;
    const int m_base  = blockIdx.x * BM;
    const int nhalf   = blockIdx.y;            // oc half (0 / 1)
    const int oc_base = nhalf * BN;

    // ---- A gather mapping ----
    const int a_m    = tid & 127;
    const int a_kq   = (tid >> 7) * 16;        // k_local base: 0 or 16
    const int tile_m = a_m >> 4;
    const int grp_w  = a_m & 7;
    const int half_w = (a_m >> 3) & 1;
    const int xr     = (tile_m & 1) * 4;       // bank-conflict break for STS
    const int m_g    = m_base + a_m;
    const int n_img  = m_g / HW;
    const int hw     = m_g - n_img * HW;
    const int h      = hw / W_DIM;
    const int w      = hw - h * W_DIM;
    const float* in_t_n = g_in_t + (size_t)n_img * (C_IN * HW) + hw;

    // per-thread A dst constants (word units); kl = a_kq + (j^xr)
    // word = ((kl>>3)*8 + tile_m)*128 + ((kl&3)*8 + grp)*4 + half + 2*((kl>>2)&1)

    // ---- loader state (stage lt, tap = lt>>2) ----
    int lt = 0, lr = 0, lsq = 0;
    auto load_next = [&]() {
        const uint32_t abase = sbase + (lt % 3) * STAGE_BYTES;
        const uint32_t bbase = abase + 16384;
        // A: one tap, 16 consecutive channels
        const bool ok = ((unsigned)(h + lr - 1) < (unsigned)H_DIM) &&
                        ((unsigned)(w + lsq - 1) < (unsigned)W_DIM);
        const uint32_t sz = ok ? 4u : 0u;
        const float* p = in_t_n + (lr - 1) * W_DIM + (lsq - 1)
                       + (size_t)((lt & 3) * 32 + a_kq) * HW;
        #pragma unroll
        for (int j = 0; j < 16; j++) {
            const int jj = j ^ xr;
            const int kl = a_kq + jj;
            const uint32_t dw = (uint32_t)(((kl >> 3) * 8 + tile_m) * 128
                               + ((kl & 3) * 8 + grp_w) * 4
                               + half_w + 2 * ((kl >> 2) & 1));
            cp4_zfill(abase + dw * 4, p + (size_t)jj * HW, sz);
        }
        // B: contiguous copy of pre-fragmented weights (16KB per stage/half)
        const uint32_t* wsrc = g_w_t + (size_t)(lt * 2 + nhalf) * 4096;
        #pragma unroll
        for (int j = 0; j < 4; j++) {
            const int cchunk = tid + 256 * j;
            cp16(bbase + cchunk * 16, wsrc + cchunk * 4);
        }
        asm volatile("cp.async.commit_group;" ::: "memory");
        lt++;
        if ((lt & 3) == 0) { lsq++; if (lsq == 3) { lsq = 0; lr++; } }
    };

    // ---- compute mapping: 4(M) x 2(N) warps, warp tile 32x64 ----
    const int wm  = wid & 3;
    const int wn  = wid >> 2;
    const int grp = lane >> 2;
    const int tig = lane & 3;
    const uint32_t a_roff = (uint32_t)((tig * 8 + grp) * 16);   // bytes
    const uint32_t b_roff = (uint32_t)(grp * 64 + tig * 16);    // bytes

    float acc[2][8][4];
    #pragma unroll
    for (int mi = 0; mi < 2; mi++)
        #pragma unroll
        for (int ni = 0; ni < 8; ni++)
            #pragma unroll
            for (int q = 0; q < 4; q++) acc[mi][ni][q] = 0.0f;

    load_next(); load_next(); load_next();

    int buf = 0;
    for (int s = 0; s < NSTAGES; s++) {
        asm volatile("cp.async.wait_group 2;" ::: "memory");
        __syncthreads();

        const uint32_t Ab = sbase + buf * STAGE_BYTES;
        const uint32_t Bb = Ab + 16384;
        #pragma unroll
        for (int ks = 0; ks < 4; ks++) {
            uint32_t a[2][4];
            #pragma unroll
            for (int mi = 0; mi < 2; mi++)
                lds128(a[mi], Ab + (uint32_t)((ks * 8 + wm * 2 + mi) * 512) + a_roff);
            uint32_t bb[4][4];
            #pragma unroll
            for (int t = 0; t < 4; t++)
                lds128(bb[t], Bb + (uint32_t)((ks * 8 + wn * 4 + t) * 512) + b_roff);
            #pragma unroll
            for (int t = 0; t < 4; t++)
                #pragma unroll
                for (int tpo = 0; tpo < 2; tpo++) {
                    const int ni = t * 2 + tpo;
                    #pragma unroll
                    for (int mi = 0; mi < 2; mi++)
                        mma_tf32(acc[mi][ni], a[mi], bb[t][tpo * 2], bb[t][tpo * 2 + 1]);
                }
        }
        __syncthreads();

        if (s + 3 < NSTAGES) load_next();
        else asm volatile("cp.async.commit_group;" ::: "memory");

        buf = (buf == 2) ? 0 : buf + 1;
    }

    // ---- epilogue: +bias (fp32), scatter to NCHW ----
    #pragma unroll
    for (int mi = 0; mi < 2; mi++) {
        const int row0 = m_base + wm * 32 + mi * 16 + grp;
        #pragma unroll
        for (int hf = 0; hf < 2; hf++) {
            const int m   = row0 + 8 * hf;
            const int nn  = m / HW;
            const int phw = m - nn * HW;
            float* op = out + (size_t)nn * OC_DIM * HW + phw;
            #pragma unroll
            for (int ni = 0; ni < 8; ni++) {
                const int oc = oc_base + wn * 64 + ni * 8 + 2 * tig;
                const float b0 = __ldg(bias + oc);
                const float b1 = __ldg(bias + oc + 1);
                op[(size_t)oc * HW]       = acc[mi][ni][2 * hf + 0] + b0;
                op[(size_t)(oc + 1) * HW] = acc[mi][ni][2 * hf + 1] + b1;
            }
        }
    }
}

extern "C" void kernel_launch(void* const* d_in, const int* in_sizes, int n_in,
                              void* d_out, int out_size)
{
    const float* in   = (const float*)d_in[0];
    const float* wgt  = (const float*)d_in[1];
    const float* bias = (const float*)d_in[2];
    float* out        = (float*)d_out;

    prep_in_kernel<<<(N_IMG * C_IN * HW / 4) / 256, 256>>>(in);
    prep_w_kernel<<<(OC_DIM * K_TOTAL) / 256, 256>>>(wgt);

    cudaFuncSetAttribute(conv2d_mma_kernel,
                         cudaFuncAttributeMaxDynamicSharedMemorySize, SMEM_TOTAL);
    dim3 grid(M_TOTAL / BM, OC_DIM / BN, 1);   // 784 x 2
    conv2d_mma_kernel<<<grid, THREADS, SMEM_TOTAL>>>(bias, out);
}